// round 1
// baseline (speedup 1.0000x reference)
#include <cuda_runtime.h>
#include <cuda_bf16.h>

#define N_NODES 50000
#define N_EDGES 800000
#define DIM 96
#define N_LAYERS 4
#define N_GRAPHS 256
#define BN_EPS 1e-5f

// ---------------- device scratch (no allocations allowed) ----------------
__device__ float g_hw[N_NODES * DIM];    // h @ W
__device__ float g_agg[N_NODES * DIM];   // aggregated output of GCN layer
__device__ float g_dis[N_NODES];         // 1/sqrt(deg)
__device__ float g_deg[N_NODES];
__device__ float g_stats[2 * DIM];       // BN sum / sumsq accumulators
__device__ float g_bn[2 * DIM];          // BN affine: a = rsig*gamma, c = beta - mu*a
__device__ float g_cnt[N_GRAPHS];        // nodes per graph

// ---------------- init: deg=1 (self loop), zero stats/cnt/out ----------------
__global__ void init_kernel(float* out) {
    int i = blockIdx.x * blockDim.x + threadIdx.x;
    if (i < N_NODES) g_deg[i] = 1.0f;
    if (i < 2 * DIM) g_stats[i] = 0.0f;
    if (i < N_GRAPHS) g_cnt[i] = 0.0f;
    if (i < N_GRAPHS * DIM) out[i] = 0.0f;
}

// ---------------- degree (in-degree over dst) + graph node counts ----------------
__global__ void deg_kernel(const int* __restrict__ dst, const int* __restrict__ batch) {
    int i = blockIdx.x * blockDim.x + threadIdx.x;
    int stride = gridDim.x * blockDim.x;
    for (int e = i; e < N_EDGES; e += stride)
        atomicAdd(&g_deg[dst[e]], 1.0f);
    for (int v = i; v < N_NODES; v += stride)
        atomicAdd(&g_cnt[batch[v]], 1.0f);
}

__global__ void dis_kernel() {
    int v = blockIdx.x * blockDim.x + threadIdx.x;
    if (v < N_NODES) g_dis[v] = rsqrtf(g_deg[v]);  // deg >= 1 always
}

// ---------------- GEMM: out rows = in rows @ W; epilogue writes hw and agg init ----
// If apply_bn: input element is first transformed relu(v*a[c] + c[c]) (BN of prev layer).
#define GEMM_ROWS 32
__global__ __launch_bounds__(384) void gemm_kernel(const float* __restrict__ in,
                                                   const float* __restrict__ Wl,
                                                   const float* __restrict__ bl,
                                                   int apply_bn) {
    __shared__ float Ws[DIM * DIM];        // 36 KB
    __shared__ float Hs[GEMM_ROWS][DIM];   // 12 KB

    int t = threadIdx.x;
    for (int i = t; i < DIM * DIM; i += 384) Ws[i] = Wl[i];

    int row0 = blockIdx.x * GEMM_ROWS;
    for (int i = t; i < GEMM_ROWS * DIM; i += 384) {
        int r = i / DIM, c = i % DIM;
        int rr = row0 + r;
        float v = (rr < N_NODES) ? in[rr * DIM + c] : 0.0f;
        if (apply_bn) v = fmaxf(v * g_bn[c] + g_bn[DIM + c], 0.0f);
        Hs[r][c] = v;
    }
    __syncthreads();

    int c  = t % DIM;   // 0..95 ; warp-aligned since 96 % 32 == 0
    int ry = t / DIM;   // 0..3
    float acc[8];
#pragma unroll
    for (int j = 0; j < 8; j++) acc[j] = 0.0f;

#pragma unroll 4
    for (int k = 0; k < DIM; k++) {
        float w = Ws[k * DIM + c];
#pragma unroll
        for (int j = 0; j < 8; j++)
            acc[j] = fmaf(Hs[ry + 4 * j][k], w, acc[j]);
    }

    float bc = bl[c];
#pragma unroll
    for (int j = 0; j < 8; j++) {
        int rr = row0 + ry + 4 * j;
        if (rr < N_NODES) {
            float v = acc[j];
            g_hw[rr * DIM + c] = v;
            float dv = g_dis[rr];
            g_agg[rr * DIM + c] = v * dv * dv + bc;  // self-loop + bias
        }
    }
}

// ---------------- edge scatter: one warp per edge, 3 dims per lane ----------------
__global__ __launch_bounds__(256) void scatter_kernel(const int* __restrict__ src,
                                                      const int* __restrict__ dst) {
    int warp = (blockIdx.x * blockDim.x + threadIdx.x) >> 5;
    if (warp >= N_EDGES) return;
    int lane = threadIdx.x & 31;
    int s = src[warp];
    int d = dst[warp];
    float nrm = g_dis[s] * g_dis[d];
    const float* __restrict__ hs = &g_hw[(size_t)s * DIM];
    float* ad = &g_agg[(size_t)d * DIM];
#pragma unroll
    for (int j = 0; j < 3; j++) {
        int cc = lane + 32 * j;
        atomicAdd(&ad[cc], hs[cc] * nrm);
    }
}

// ---------------- BN statistics: per-column sum & sumsq ----------------
__global__ __launch_bounds__(384) void bnstats_kernel() {
    int c = threadIdx.x;   // 0..95
    int ty = threadIdx.y;  // 0..3
    int r0 = blockIdx.x * 256;
    int rend = r0 + 256; if (rend > N_NODES) rend = N_NODES;
    float s = 0.0f, s2 = 0.0f;
    for (int r = r0 + ty; r < rend; r += 4) {
        float v = g_agg[r * DIM + c];
        s += v; s2 = fmaf(v, v, s2);
    }
    __shared__ float sh[4][DIM], sh2[4][DIM];
    sh[ty][c] = s; sh2[ty][c] = s2;
    __syncthreads();
    if (ty == 0) {
        s  = sh[0][c] + sh[1][c] + sh[2][c] + sh[3][c];
        s2 = sh2[0][c] + sh2[1][c] + sh2[2][c] + sh2[3][c];
        atomicAdd(&g_stats[c], s);
        atomicAdd(&g_stats[DIM + c], s2);
    }
}

__global__ void bn_finalize_kernel(const float* __restrict__ gamma,
                                   const float* __restrict__ beta) {
    int c = threadIdx.x;  // 96 threads
    if (c >= DIM) return;
    float mu  = g_stats[c] * (1.0f / N_NODES);
    float var = g_stats[DIM + c] * (1.0f / N_NODES) - mu * mu;
    float rs  = rsqrtf(var + BN_EPS);
    float a   = rs * gamma[c];
    g_bn[c] = a;
    g_bn[DIM + c] = beta[c] - mu * a;
    g_stats[c] = 0.0f;           // ready for next layer
    g_stats[DIM + c] = 0.0f;
}

// ---------------- pooling: BN-apply + ReLU + segment sum (sorted batch) --------
__global__ __launch_bounds__(384) void pool_kernel(const int* __restrict__ batch,
                                                   float* __restrict__ out) {
    int c = threadIdx.x;   // 0..95
    int ty = threadIdx.y;  // 0..3
    int r0 = blockIdx.x * 128;
    int rend = r0 + 128; if (rend > N_NODES) rend = N_NODES;
    float a = g_bn[c], cc = g_bn[DIM + c];
    float acc = 0.0f;
    int cg = -1;
    for (int r = r0 + ty; r < rend; r += 4) {
        float v = fmaxf(g_agg[r * DIM + c] * a + cc, 0.0f);
        int g = batch[r];
        if (g != cg) {
            if (cg >= 0) atomicAdd(&out[cg * DIM + c], acc);
            cg = g; acc = 0.0f;
        }
        acc += v;
    }
    if (cg >= 0) atomicAdd(&out[cg * DIM + c], acc);
}

__global__ void pool_div_kernel(float* __restrict__ out) {
    int i = blockIdx.x * blockDim.x + threadIdx.x;
    if (i < N_GRAPHS * DIM) {
        float cnt = g_cnt[i / DIM];
        out[i] = out[i] / fmaxf(cnt, 1.0f);
    }
}

// ---------------- launch ----------------
extern "C" void kernel_launch(void* const* d_in, const int* in_sizes, int n_in,
                              void* d_out, int out_size) {
    const float* x        = (const float*)d_in[0];
    const int*   eidx     = (const int*)d_in[1];
    const int*   batch    = (const int*)d_in[2];
    const float* W        = (const float*)d_in[3];
    const float* b        = (const float*)d_in[4];
    const float* gamma    = (const float*)d_in[5];
    const float* beta     = (const float*)d_in[6];
    float* out = (float*)d_out;

    const int* src = eidx;
    const int* dst = eidx + N_EDGES;

    init_kernel<<<(N_NODES + 255) / 256, 256>>>(out);
    deg_kernel<<<512, 256>>>(dst, batch);
    dis_kernel<<<(N_NODES + 255) / 256, 256>>>();

    dim3 bn_blk(96, 4);
    int gemm_grid = (N_NODES + GEMM_ROWS - 1) / GEMM_ROWS;
    int scat_grid = (N_EDGES * 32 + 255) / 256;
    int stats_grid = (N_NODES + 255) / 256;

    for (int l = 0; l < N_LAYERS; l++) {
        const float* in = (l == 0) ? x : g_agg;  // resolved below via flag
        // note: g_agg is a __device__ symbol; get its address via a kernel-side
        // constant is not possible from host without cudaGetSymbolAddress (allowed,
        // not an allocation) — but simpler: pass flag and read g_agg inside.
        (void)in;
        if (l == 0) {
            gemm_kernel<<<gemm_grid, 384>>>(x, W + l * DIM * DIM, b + l * DIM, 0);
        } else {
            // input comes from g_agg with BN applied inside the kernel; pass the
            // device-symbol address obtained at first launch setup:
            static float* agg_ptr = nullptr;
            if (!agg_ptr) cudaGetSymbolAddress((void**)&agg_ptr, g_agg);
            gemm_kernel<<<gemm_grid, 384>>>(agg_ptr, W + l * DIM * DIM, b + l * DIM, 1);
        }
        scatter_kernel<<<scat_grid, 256>>>(src, dst);
        bnstats_kernel<<<stats_grid, bn_blk>>>();
        bn_finalize_kernel<<<1, 96>>>(gamma + l * DIM, beta + l * DIM);
    }

    pool_kernel<<<(N_NODES + 127) / 128, bn_blk>>>(batch, out);
    pool_div_kernel<<<(N_GRAPHS * DIM + 255) / 256, 256>>>(out);
}

// round 2
// speedup vs baseline: 1.1299x; 1.1299x over previous
#include <cuda_runtime.h>
#include <cuda_bf16.h>

#define N_NODES 50000
#define N_EDGES 800000
#define DIM 96
#define N_LAYERS 4
#define N_GRAPHS 256
#define BN_EPS 1e-5f

// ---------------- device scratch (no allocations allowed) ----------------
__device__ float g_hw[N_NODES * DIM];     // h @ W
__device__ float g_agg[N_NODES * DIM];    // layer output pre-BN
__device__ float g_dis[N_NODES];          // 1/sqrt(deg)
__device__ int   g_count[N_NODES];        // in-degree (excl. self loop)
__device__ int   g_off[N_NODES + 1];      // CSR row offsets
__device__ int   g_cursor[N_NODES];       // fill cursors
__device__ int   g_csr_src[N_EDGES];      // src ids grouped by dst
__device__ float g_stats[2 * DIM];        // BN sum / sumsq
__device__ float g_bn[2 * DIM];           // BN affine: a, c  (y = a*x + c)
__device__ float g_cnt[N_GRAPHS];         // nodes per graph

// ---------------- init ----------------
__global__ void init_kernel(float* out) {
    int i = blockIdx.x * blockDim.x + threadIdx.x;
    if (i < N_NODES) g_count[i] = 0;
    if (i < 2 * DIM) g_stats[i] = 0.0f;
    if (i < N_GRAPHS) g_cnt[i] = 0.0f;
    if (i < N_GRAPHS * DIM) out[i] = 0.0f;
}

// ---------------- degree histogram + graph node counts ----------------
__global__ void deg_kernel(const int* __restrict__ dst, const int* __restrict__ batch) {
    int i = blockIdx.x * blockDim.x + threadIdx.x;
    int stride = gridDim.x * blockDim.x;
    for (int e = i; e < N_EDGES; e += stride)
        atomicAdd(&g_count[dst[e]], 1);
    for (int v = i; v < N_NODES; v += stride)
        atomicAdd(&g_cnt[batch[v]], 1.0f);
}

__global__ void dis_kernel() {
    int v = blockIdx.x * blockDim.x + threadIdx.x;
    if (v < N_NODES) g_dis[v] = rsqrtf((float)(g_count[v] + 1));  // + self loop
}

// ---------------- single-block exclusive scan over 50k counts ----------------
__global__ __launch_bounds__(1024) void scan_kernel() {
    __shared__ int warp_sums[32];
    const int T = 1024;
    const int CH = (N_NODES + T - 1) / T;  // 49
    int t = threadIdx.x;
    int base = t * CH;
    int s = 0;
    for (int i = 0; i < CH; i++) {
        int idx = base + i;
        if (idx < N_NODES) s += g_count[idx];
    }
    int lane = t & 31, wid = t >> 5;
    int v = s;
#pragma unroll
    for (int o = 1; o < 32; o <<= 1) {
        int n = __shfl_up_sync(0xffffffffu, v, o);
        if (lane >= o) v += n;
    }
    if (lane == 31) warp_sums[wid] = v;
    __syncthreads();
    if (wid == 0) {
        int w = warp_sums[lane];
#pragma unroll
        for (int o = 1; o < 32; o <<= 1) {
            int n = __shfl_up_sync(0xffffffffu, w, o);
            if (lane >= o) w += n;
        }
        warp_sums[lane] = w;
    }
    __syncthreads();
    int excl = v - s + (wid > 0 ? warp_sums[wid - 1] : 0);
    int run = excl;
    for (int i = 0; i < CH; i++) {
        int idx = base + i;
        if (idx < N_NODES) {
            g_off[idx] = run;
            g_cursor[idx] = run;
            run += g_count[idx];
        }
    }
    if (t == T - 1) g_off[N_NODES] = run;
}

__global__ void csr_fill_kernel(const int* __restrict__ src, const int* __restrict__ dst) {
    int e = blockIdx.x * blockDim.x + threadIdx.x;
    if (e < N_EDGES) {
        int d = dst[e];
        int pos = atomicAdd(&g_cursor[d], 1);
        g_csr_src[pos] = src[e];
    }
}

// ---------------- GEMM: g_hw[rows] = act(in[rows]) @ W ----------------
// 64x96 tile, 384 threads, each thread: 8 rows x 2 cols in registers.
// H stored transposed in smem (Ht[k][row], stride 68 floats for 16B alignment).
#define TR 64
#define HT_STRIDE (TR + 4)
#define GEMM_SMEM ((DIM * DIM + DIM * HT_STRIDE) * 4)

__global__ __launch_bounds__(384) void gemm_kernel(const float* __restrict__ in,
                                                   const float* __restrict__ Wl,
                                                   int apply_bn) {
    extern __shared__ float smem[];
    float* Ws = smem;                              // [96][96]
    float* Ht = smem + DIM * DIM;                  // [96][68]

    int t = threadIdx.x;
    for (int i = t; i < DIM * DIM; i += 384) Ws[i] = Wl[i];

    const float* __restrict__ inp = apply_bn ? g_agg : in;
    int row0 = blockIdx.x * TR;
    for (int i = t; i < TR * DIM; i += 384) {
        int r = i / DIM, c = i % DIM;
        int rr = row0 + r;
        float v = (rr < N_NODES) ? inp[(size_t)rr * DIM + c] : 0.0f;
        if (apply_bn) v = fmaxf(fmaf(v, g_bn[c], g_bn[DIM + c]), 0.0f);
        Ht[c * HT_STRIDE + r] = v;
    }
    __syncthreads();

    int cp = t % 48;        // column pair id
    int rg = t / 48;        // row group 0..7
    int c0 = cp * 2;
    int r0 = rg * 8;

    float acc[8][2];
#pragma unroll
    for (int j = 0; j < 8; j++) { acc[j][0] = 0.0f; acc[j][1] = 0.0f; }

#pragma unroll 4
    for (int k = 0; k < DIM; k++) {
        float2 w = *(const float2*)&Ws[k * DIM + c0];
        float4 h0 = *(const float4*)&Ht[k * HT_STRIDE + r0];
        float4 h1 = *(const float4*)&Ht[k * HT_STRIDE + r0 + 4];
        float hv[8] = {h0.x, h0.y, h0.z, h0.w, h1.x, h1.y, h1.z, h1.w};
#pragma unroll
        for (int j = 0; j < 8; j++) {
            acc[j][0] = fmaf(hv[j], w.x, acc[j][0]);
            acc[j][1] = fmaf(hv[j], w.y, acc[j][1]);
        }
    }

#pragma unroll
    for (int j = 0; j < 8; j++) {
        int rr = row0 + r0 + j;
        if (rr < N_NODES)
            *(float2*)&g_hw[(size_t)rr * DIM + c0] = make_float2(acc[j][0], acc[j][1]);
    }
}

// ---------------- gather: agg[d] = sum_{s in N(d)} hw[s]*dis[s]*dis[d]
//                                   + hw[d]*dis[d]^2 + b
// One warp per node; fused BN statistics accumulation. ----------------
__global__ __launch_bounds__(256) void gather_kernel(const float* __restrict__ bl) {
    __shared__ float ssum[DIM], ssq[DIM];
    int t = threadIdx.x;
    if (t < DIM) { ssum[t] = 0.0f; ssq[t] = 0.0f; }
    __syncthreads();

    int warp = t >> 5, lane = t & 31;
    int node = blockIdx.x * 8 + warp;
    if (node < N_NODES) {
        int roff = g_off[node];
        int rend = g_off[node + 1];
        float a0 = 0.0f, a1 = 0.0f, a2 = 0.0f;
        int j = roff;
        for (; j + 2 <= rend; j += 2) {
            int s0 = g_csr_src[j];
            int s1 = g_csr_src[j + 1];
            float d0 = g_dis[s0];
            float d1 = g_dis[s1];
            const float* r0p = &g_hw[(size_t)s0 * DIM];
            const float* r1p = &g_hw[(size_t)s1 * DIM];
            float v00 = r0p[lane],      v10 = r1p[lane];
            float v01 = r0p[lane + 32], v11 = r1p[lane + 32];
            float v02 = r0p[lane + 64], v12 = r1p[lane + 64];
            a0 = fmaf(v00, d0, fmaf(v10, d1, a0));
            a1 = fmaf(v01, d0, fmaf(v11, d1, a1));
            a2 = fmaf(v02, d0, fmaf(v12, d1, a2));
        }
        if (j < rend) {
            int s0 = g_csr_src[j];
            float d0 = g_dis[s0];
            const float* r0p = &g_hw[(size_t)s0 * DIM];
            a0 = fmaf(r0p[lane],      d0, a0);
            a1 = fmaf(r0p[lane + 32], d0, a1);
            a2 = fmaf(r0p[lane + 64], d0, a2);
        }
        float dd = g_dis[node];
        float dd2 = dd * dd;
        const float* srow = &g_hw[(size_t)node * DIM];
        a0 = fmaf(a0, dd, fmaf(srow[lane],      dd2, bl[lane]));
        a1 = fmaf(a1, dd, fmaf(srow[lane + 32], dd2, bl[lane + 32]));
        a2 = fmaf(a2, dd, fmaf(srow[lane + 64], dd2, bl[lane + 64]));
        float* arow = &g_agg[(size_t)node * DIM];
        arow[lane] = a0; arow[lane + 32] = a1; arow[lane + 64] = a2;
        atomicAdd(&ssum[lane],      a0); atomicAdd(&ssq[lane],      a0 * a0);
        atomicAdd(&ssum[lane + 32], a1); atomicAdd(&ssq[lane + 32], a1 * a1);
        atomicAdd(&ssum[lane + 64], a2); atomicAdd(&ssq[lane + 64], a2 * a2);
    }
    __syncthreads();
    if (t < DIM) {
        atomicAdd(&g_stats[t], ssum[t]);
        atomicAdd(&g_stats[DIM + t], ssq[t]);
    }
}

__global__ void bn_finalize_kernel(const float* __restrict__ gamma,
                                   const float* __restrict__ beta) {
    int c = threadIdx.x;
    if (c >= DIM) return;
    float mu  = g_stats[c] * (1.0f / N_NODES);
    float var = g_stats[DIM + c] * (1.0f / N_NODES) - mu * mu;
    float rs  = rsqrtf(var + BN_EPS);
    float a   = rs * gamma[c];
    g_bn[c] = a;
    g_bn[DIM + c] = beta[c] - mu * a;
    g_stats[c] = 0.0f;
    g_stats[DIM + c] = 0.0f;
}

// ---------------- pooling: BN + ReLU + segment mean (sorted batch) --------
__global__ __launch_bounds__(384) void pool_kernel(const int* __restrict__ batch,
                                                   float* __restrict__ out) {
    int c = threadIdx.x;   // 0..95
    int ty = threadIdx.y;  // 0..3
    int r0 = blockIdx.x * 128;
    int rend = r0 + 128; if (rend > N_NODES) rend = N_NODES;
    float a = g_bn[c], cc = g_bn[DIM + c];
    float acc = 0.0f;
    int cg = -1;
    for (int r = r0 + ty; r < rend; r += 4) {
        float v = fmaxf(fmaf(g_agg[(size_t)r * DIM + c], a, cc), 0.0f);
        int g = batch[r];
        if (g != cg) {
            if (cg >= 0) atomicAdd(&out[cg * DIM + c], acc);
            cg = g; acc = 0.0f;
        }
        acc += v;
    }
    if (cg >= 0) atomicAdd(&out[cg * DIM + c], acc);
}

__global__ void pool_div_kernel(float* __restrict__ out) {
    int i = blockIdx.x * blockDim.x + threadIdx.x;
    if (i < N_GRAPHS * DIM) {
        float cnt = g_cnt[i / DIM];
        out[i] = out[i] / fmaxf(cnt, 1.0f);
    }
}

// ---------------- launch ----------------
extern "C" void kernel_launch(void* const* d_in, const int* in_sizes, int n_in,
                              void* d_out, int out_size) {
    const float* x     = (const float*)d_in[0];
    const int*   eidx  = (const int*)d_in[1];
    const int*   batch = (const int*)d_in[2];
    const float* W     = (const float*)d_in[3];
    const float* b     = (const float*)d_in[4];
    const float* gamma = (const float*)d_in[5];
    const float* beta  = (const float*)d_in[6];
    float* out = (float*)d_out;

    const int* src = eidx;
    const int* dst = eidx + N_EDGES;

    static bool configured = false;
    if (!configured) {
        cudaFuncSetAttribute(gemm_kernel,
                             cudaFuncAttributeMaxDynamicSharedMemorySize, GEMM_SMEM);
        configured = true;
    }

    init_kernel<<<(N_NODES + 255) / 256, 256>>>(out);
    deg_kernel<<<512, 256>>>(dst, batch);
    dis_kernel<<<(N_NODES + 255) / 256, 256>>>();
    scan_kernel<<<1, 1024>>>();
    csr_fill_kernel<<<(N_EDGES + 255) / 256, 256>>>(src, dst);

    int gemm_grid = (N_NODES + TR - 1) / TR;
    int gather_grid = (N_NODES + 7) / 8;

    for (int l = 0; l < N_LAYERS; l++) {
        gemm_kernel<<<gemm_grid, 384, GEMM_SMEM>>>(x, W + l * DIM * DIM, l > 0);
        gather_kernel<<<gather_grid, 256>>>(b + l * DIM);
        bn_finalize_kernel<<<1, 96>>>(gamma + l * DIM, beta + l * DIM);
    }

    dim3 pool_blk(96, 4);
    pool_kernel<<<(N_NODES + 127) / 128, pool_blk>>>(batch, out);
    pool_div_kernel<<<(N_GRAPHS * DIM + 255) / 256, 256>>>(out);
}

// round 3
// speedup vs baseline: 1.3741x; 1.2161x over previous
#include <cuda_runtime.h>
#include <cuda_bf16.h>

#define N_NODES 50000
#define N_EDGES 800000
#define DIM 96
#define N_LAYERS 4
#define N_GRAPHS 256
#define BN_EPS 1e-5f
#define SCAN_BLOCKS ((N_NODES + 255) / 256)   // 196

// ---------------- device scratch (no allocations allowed) ----------------
__device__ float g_hw[N_NODES * DIM];     // h @ W
__device__ float g_agg[N_NODES * DIM];    // layer output pre-BN
__device__ float g_dis[N_NODES];          // 1/sqrt(deg)
__device__ int   g_count[N_NODES];        // in-degree (excl. self loop)
__device__ int   g_off[N_NODES + 1];      // CSR row offsets
__device__ int   g_cursor[N_NODES];       // fill cursors
__device__ int   g_csr_src[N_EDGES];      // src ids grouped by dst
__device__ int   g_bsum[SCAN_BLOCKS];     // scan phase partials
__device__ int   g_bpre[SCAN_BLOCKS];     // scanned partials
__device__ float g_stats[2 * DIM];        // BN sum / sumsq
__device__ float g_bn[2 * DIM];           // BN affine: a, c  (y = a*x + c)
__device__ float g_cnt[N_GRAPHS];         // nodes per graph

// ---------------- init ----------------
__global__ void init_kernel(float* out) {
    int i = blockIdx.x * blockDim.x + threadIdx.x;
    if (i < N_NODES) g_count[i] = 0;
    if (i < 2 * DIM) g_stats[i] = 0.0f;
    if (i < N_GRAPHS) g_cnt[i] = 0.0f;
    if (i < N_GRAPHS * DIM) out[i] = 0.0f;
}

// ---------------- degree histogram + graph node counts ----------------
__global__ void deg_kernel(const int* __restrict__ dst, const int* __restrict__ batch) {
    int i = blockIdx.x * blockDim.x + threadIdx.x;
    int stride = gridDim.x * blockDim.x;
    for (int e = i; e < N_EDGES; e += stride)
        atomicAdd(&g_count[dst[e]], 1);
    for (int v = i; v < N_NODES; v += stride)
        atomicAdd(&g_cnt[batch[v]], 1.0f);
}

// ---------------- scan phase A: per-block partial sums + dis ----------------
__global__ __launch_bounds__(256) void scanA_kernel() {
    __shared__ int wsum[8];
    int idx = blockIdx.x * 256 + threadIdx.x;
    int c = 0;
    if (idx < N_NODES) {
        c = g_count[idx];
        g_dis[idx] = rsqrtf((float)(c + 1));   // + self loop
    }
    int lane = threadIdx.x & 31, wid = threadIdx.x >> 5;
    int v = c;
#pragma unroll
    for (int o = 16; o > 0; o >>= 1) v += __shfl_down_sync(0xffffffffu, v, o);
    if (lane == 0) wsum[wid] = v;
    __syncthreads();
    if (threadIdx.x == 0) {
        int s = 0;
#pragma unroll
        for (int w = 0; w < 8; w++) s += wsum[w];
        g_bsum[blockIdx.x] = s;
    }
}

// ---------------- scan phase B: scan 196 partials (1 block) ----------------
__global__ __launch_bounds__(256) void scanB_kernel() {
    __shared__ int wsum[8];
    int t = threadIdx.x;
    int v = (t < SCAN_BLOCKS) ? g_bsum[t] : 0;
    int lane = t & 31, wid = t >> 5;
    int inc = v;
#pragma unroll
    for (int o = 1; o < 32; o <<= 1) {
        int n = __shfl_up_sync(0xffffffffu, inc, o);
        if (lane >= o) inc += n;
    }
    if (lane == 31) wsum[wid] = inc;
    __syncthreads();
    if (wid == 0 && lane < 8) {
        int w = wsum[lane];
#pragma unroll
        for (int o = 1; o < 8; o <<= 1) {
            int n = __shfl_up_sync(0xffu, w, o);
            if (lane >= o) w += n;
        }
        wsum[lane] = w;
    }
    __syncthreads();
    int incl = inc + (wid > 0 ? wsum[wid - 1] : 0);
    if (t < SCAN_BLOCKS) g_bpre[t] = incl - v;   // exclusive
    if (t == 255) g_off[N_NODES] = wsum[7];      // total
}

// ---------------- scan phase C: per-block local scan + offsets ----------------
__global__ __launch_bounds__(256) void scanC_kernel() {
    __shared__ int wsum[8];
    int idx = blockIdx.x * 256 + threadIdx.x;
    int c = (idx < N_NODES) ? g_count[idx] : 0;
    int lane = threadIdx.x & 31, wid = threadIdx.x >> 5;
    int inc = c;
#pragma unroll
    for (int o = 1; o < 32; o <<= 1) {
        int n = __shfl_up_sync(0xffffffffu, inc, o);
        if (lane >= o) inc += n;
    }
    if (lane == 31) wsum[wid] = inc;
    __syncthreads();
    if (wid == 0 && lane < 8) {
        int w = wsum[lane];
#pragma unroll
        for (int o = 1; o < 8; o <<= 1) {
            int n = __shfl_up_sync(0xffu, w, o);
            if (lane >= o) w += n;
        }
        wsum[lane] = w;
    }
    __syncthreads();
    int excl = inc - c + (wid > 0 ? wsum[wid - 1] : 0) + g_bpre[blockIdx.x];
    if (idx < N_NODES) {
        g_off[idx] = excl;
        g_cursor[idx] = excl;
    }
}

__global__ void csr_fill_kernel(const int* __restrict__ src, const int* __restrict__ dst) {
    int e = blockIdx.x * blockDim.x + threadIdx.x;
    if (e < N_EDGES) {
        int d = dst[e];
        int pos = atomicAdd(&g_cursor[d], 1);
        g_csr_src[pos] = src[e];
    }
}

// ---------------- GEMM: g_hw[rows] = act(in[rows]) @ W ----------------
#define TR 64
#define HT_STRIDE (TR + 4)
#define GEMM_SMEM ((DIM * DIM + DIM * HT_STRIDE) * 4)

__global__ __launch_bounds__(384) void gemm_kernel(const float* __restrict__ in,
                                                   const float* __restrict__ Wl,
                                                   int apply_bn) {
    extern __shared__ float smem[];
    float* Ws = smem;                              // [96][96]
    float* Ht = smem + DIM * DIM;                  // [96][68]

    int t = threadIdx.x;
    for (int i = t; i < DIM * DIM; i += 384) Ws[i] = Wl[i];

    const float* __restrict__ inp = apply_bn ? g_agg : in;
    int row0 = blockIdx.x * TR;
    for (int i = t; i < TR * DIM; i += 384) {
        int r = i / DIM, c = i % DIM;
        int rr = row0 + r;
        float v = (rr < N_NODES) ? inp[(size_t)rr * DIM + c] : 0.0f;
        if (apply_bn) v = fmaxf(fmaf(v, g_bn[c], g_bn[DIM + c]), 0.0f);
        Ht[c * HT_STRIDE + r] = v;
    }
    __syncthreads();

    int cp = t % 48;        // column pair id
    int rg = t / 48;        // row group 0..7
    int c0 = cp * 2;
    int r0 = rg * 8;

    float acc[8][2];
#pragma unroll
    for (int j = 0; j < 8; j++) { acc[j][0] = 0.0f; acc[j][1] = 0.0f; }

#pragma unroll 4
    for (int k = 0; k < DIM; k++) {
        float2 w = *(const float2*)&Ws[k * DIM + c0];
        float4 h0 = *(const float4*)&Ht[k * HT_STRIDE + r0];
        float4 h1 = *(const float4*)&Ht[k * HT_STRIDE + r0 + 4];
        float hv[8] = {h0.x, h0.y, h0.z, h0.w, h1.x, h1.y, h1.z, h1.w};
#pragma unroll
        for (int j = 0; j < 8; j++) {
            acc[j][0] = fmaf(hv[j], w.x, acc[j][0]);
            acc[j][1] = fmaf(hv[j], w.y, acc[j][1]);
        }
    }

#pragma unroll
    for (int j = 0; j < 8; j++) {
        int rr = row0 + r0 + j;
        if (rr < N_NODES)
            *(float2*)&g_hw[(size_t)rr * DIM + c0] = make_float2(acc[j][0], acc[j][1]);
    }
}

// ---------------- gather: agg[d] = sum_{s in N(d)} hw[s]*dis[s]*dis[d]
//                                   + hw[d]*dis[d]^2 + b   (fused BN stats)
__global__ __launch_bounds__(256) void gather_kernel(const float* __restrict__ bl) {
    __shared__ float ssum[DIM], ssq[DIM];
    int t = threadIdx.x;
    if (t < DIM) { ssum[t] = 0.0f; ssq[t] = 0.0f; }
    __syncthreads();

    int warp = t >> 5, lane = t & 31;
    int node = blockIdx.x * 8 + warp;
    if (node < N_NODES) {
        int roff = g_off[node];
        int rend = g_off[node + 1];
        float a0 = 0.0f, a1 = 0.0f, a2 = 0.0f;
        int j = roff;
        for (; j + 4 <= rend; j += 4) {
            int s0 = g_csr_src[j],     s1 = g_csr_src[j + 1];
            int s2 = g_csr_src[j + 2], s3 = g_csr_src[j + 3];
            float d0 = g_dis[s0], d1 = g_dis[s1], d2 = g_dis[s2], d3 = g_dis[s3];
            const float* p0 = &g_hw[(size_t)s0 * DIM];
            const float* p1 = &g_hw[(size_t)s1 * DIM];
            const float* p2 = &g_hw[(size_t)s2 * DIM];
            const float* p3 = &g_hw[(size_t)s3 * DIM];
            float v00 = p0[lane],      v10 = p1[lane],      v20 = p2[lane],      v30 = p3[lane];
            float v01 = p0[lane + 32], v11 = p1[lane + 32], v21 = p2[lane + 32], v31 = p3[lane + 32];
            float v02 = p0[lane + 64], v12 = p1[lane + 64], v22 = p2[lane + 64], v32 = p3[lane + 64];
            a0 = fmaf(v00, d0, fmaf(v10, d1, fmaf(v20, d2, fmaf(v30, d3, a0))));
            a1 = fmaf(v01, d0, fmaf(v11, d1, fmaf(v21, d2, fmaf(v31, d3, a1))));
            a2 = fmaf(v02, d0, fmaf(v12, d1, fmaf(v22, d2, fmaf(v32, d3, a2))));
        }
        for (; j < rend; j++) {
            int s0 = g_csr_src[j];
            float d0 = g_dis[s0];
            const float* p0 = &g_hw[(size_t)s0 * DIM];
            a0 = fmaf(p0[lane],      d0, a0);
            a1 = fmaf(p0[lane + 32], d0, a1);
            a2 = fmaf(p0[lane + 64], d0, a2);
        }
        float dd = g_dis[node];
        float dd2 = dd * dd;
        const float* srow = &g_hw[(size_t)node * DIM];
        a0 = fmaf(a0, dd, fmaf(srow[lane],      dd2, bl[lane]));
        a1 = fmaf(a1, dd, fmaf(srow[lane + 32], dd2, bl[lane + 32]));
        a2 = fmaf(a2, dd, fmaf(srow[lane + 64], dd2, bl[lane + 64]));
        float* arow = &g_agg[(size_t)node * DIM];
        arow[lane] = a0; arow[lane + 32] = a1; arow[lane + 64] = a2;
        atomicAdd(&ssum[lane],      a0); atomicAdd(&ssq[lane],      a0 * a0);
        atomicAdd(&ssum[lane + 32], a1); atomicAdd(&ssq[lane + 32], a1 * a1);
        atomicAdd(&ssum[lane + 64], a2); atomicAdd(&ssq[lane + 64], a2 * a2);
    }
    __syncthreads();
    if (t < DIM) {
        atomicAdd(&g_stats[t], ssum[t]);
        atomicAdd(&g_stats[DIM + t], ssq[t]);
    }
}

__global__ void bn_finalize_kernel(const float* __restrict__ gamma,
                                   const float* __restrict__ beta) {
    int c = threadIdx.x;
    if (c >= DIM) return;
    float mu  = g_stats[c] * (1.0f / N_NODES);
    float var = g_stats[DIM + c] * (1.0f / N_NODES) - mu * mu;
    float rs  = rsqrtf(var + BN_EPS);
    float a   = rs * gamma[c];
    g_bn[c] = a;
    g_bn[DIM + c] = beta[c] - mu * a;
    g_stats[c] = 0.0f;
    g_stats[DIM + c] = 0.0f;
}

// ---------------- pooling: BN + ReLU + segment mean (sorted batch) --------
__global__ __launch_bounds__(384) void pool_kernel(const int* __restrict__ batch,
                                                   float* __restrict__ out) {
    int c = threadIdx.x;   // 0..95
    int ty = threadIdx.y;  // 0..3
    int r0 = blockIdx.x * 128;
    int rend = r0 + 128; if (rend > N_NODES) rend = N_NODES;
    float a = g_bn[c], cc = g_bn[DIM + c];
    float acc = 0.0f;
    int cg = -1;
    for (int r = r0 + ty; r < rend; r += 4) {
        float v = fmaxf(fmaf(g_agg[(size_t)r * DIM + c], a, cc), 0.0f);
        int g = batch[r];
        if (g != cg) {
            if (cg >= 0) atomicAdd(&out[cg * DIM + c], acc);
            cg = g; acc = 0.0f;
        }
        acc += v;
    }
    if (cg >= 0) atomicAdd(&out[cg * DIM + c], acc);
}

__global__ void pool_div_kernel(float* __restrict__ out) {
    int i = blockIdx.x * blockDim.x + threadIdx.x;
    if (i < N_GRAPHS * DIM) {
        float cnt = g_cnt[i / DIM];
        out[i] = out[i] / fmaxf(cnt, 1.0f);
    }
}

// ---------------- launch ----------------
extern "C" void kernel_launch(void* const* d_in, const int* in_sizes, int n_in,
                              void* d_out, int out_size) {
    const float* x     = (const float*)d_in[0];
    const int*   eidx  = (const int*)d_in[1];
    const int*   batch = (const int*)d_in[2];
    const float* W     = (const float*)d_in[3];
    const float* b     = (const float*)d_in[4];
    const float* gamma = (const float*)d_in[5];
    const float* beta  = (const float*)d_in[6];
    float* out = (float*)d_out;

    const int* src = eidx;
    const int* dst = eidx + N_EDGES;

    static cudaStream_t s1 = nullptr;
    static cudaEvent_t ev_init = nullptr, ev_csr = nullptr;
    if (!s1) {
        cudaFuncSetAttribute(gemm_kernel,
                             cudaFuncAttributeMaxDynamicSharedMemorySize, GEMM_SMEM);
        cudaStreamCreateWithFlags(&s1, cudaStreamNonBlocking);
        cudaEventCreateWithFlags(&ev_init, cudaEventDisableTiming);
        cudaEventCreateWithFlags(&ev_csr, cudaEventDisableTiming);
    }

    // main (capture) stream = 0
    init_kernel<<<(N_NODES + 255) / 256, 256>>>(out);
    cudaEventRecord(ev_init, 0);

    // side stream: CSR build, overlapped with layer-0 GEMM on the main stream
    cudaStreamWaitEvent(s1, ev_init, 0);
    deg_kernel<<<512, 256, 0, s1>>>(dst, batch);
    scanA_kernel<<<SCAN_BLOCKS, 256, 0, s1>>>();
    scanB_kernel<<<1, 256, 0, s1>>>();
    scanC_kernel<<<SCAN_BLOCKS, 256, 0, s1>>>();
    csr_fill_kernel<<<(N_EDGES + 255) / 256, 256, 0, s1>>>(src, dst);
    cudaEventRecord(ev_csr, s1);

    int gemm_grid = (N_NODES + TR - 1) / TR;
    int gather_grid = (N_NODES + 7) / 8;

    gemm_kernel<<<gemm_grid, 384, GEMM_SMEM>>>(x, W, 0);
    cudaStreamWaitEvent(0, ev_csr, 0);

    for (int l = 0; l < N_LAYERS; l++) {
        if (l > 0)
            gemm_kernel<<<gemm_grid, 384, GEMM_SMEM>>>(x, W + l * DIM * DIM, 1);
        gather_kernel<<<gather_grid, 256>>>(b + l * DIM);
        bn_finalize_kernel<<<1, 96>>>(gamma + l * DIM, beta + l * DIM);
    }

    dim3 pool_blk(96, 4);
    pool_kernel<<<(N_NODES + 127) / 128, pool_blk>>>(batch, out);
    pool_div_kernel<<<(N_GRAPHS * DIM + 255) / 256, 256>>>(out);
}

// round 4
// speedup vs baseline: 1.7787x; 1.2945x over previous
#include <cuda_runtime.h>
#include <cuda_bf16.h>

#define N_NODES 50000
#define N_EDGES 800000
#define DIM 96
#define N_LAYERS 4
#define N_GRAPHS 256
#define BN_EPS 1e-5f
#define SCAN_BLOCKS ((N_NODES + 255) / 256)   // 196
#define GATHER_BLOCKS 1184                    // 148 SMs * 8

// ---------------- device scratch (no allocations allowed) ----------------
__device__ float g_hw[N_NODES * DIM];     // (h @ W) * dis[row]  (pre-scaled!)
__device__ float g_agg[N_NODES * DIM];    // layer output pre-BN
__device__ float g_dis[N_NODES];          // 1/sqrt(deg)
__device__ int   g_count[N_NODES];        // in-degree (excl. self loop)
__device__ int   g_off[N_NODES + 1];      // CSR row offsets
__device__ int   g_cursor[N_NODES];       // fill cursors
__device__ int   g_csr_src[N_EDGES];      // src ids grouped by dst
__device__ int   g_bsum[SCAN_BLOCKS];     // scan phase partials
__device__ int   g_bpre[SCAN_BLOCKS];     // scanned partials
__device__ float g_stats[2 * DIM];        // BN sum / sumsq
__device__ float g_bn[2 * DIM];           // BN affine: a, c  (y = a*x + c)
__device__ float g_cnt[N_GRAPHS];         // nodes per graph
__device__ unsigned g_done = 0;           // gather completion counter

// ---------------- init ----------------
__global__ void init_kernel(float* out) {
    int i = blockIdx.x * blockDim.x + threadIdx.x;
    if (i < N_NODES) g_count[i] = 0;
    if (i < 2 * DIM) g_stats[i] = 0.0f;
    if (i < N_GRAPHS) g_cnt[i] = 0.0f;
    if (i < N_GRAPHS * DIM) out[i] = 0.0f;
}

// ---------------- degree histogram + graph node counts ----------------
__global__ void deg_kernel(const int* __restrict__ dst, const int* __restrict__ batch) {
    int i = blockIdx.x * blockDim.x + threadIdx.x;
    int stride = gridDim.x * blockDim.x;
    for (int e = i; e < N_EDGES; e += stride)
        atomicAdd(&g_count[dst[e]], 1);
    for (int v = i; v < N_NODES; v += stride)
        atomicAdd(&g_cnt[batch[v]], 1.0f);
}

// ---------------- scan phase A: per-block partial sums + dis ----------------
__global__ __launch_bounds__(256) void scanA_kernel() {
    __shared__ int wsum[8];
    int idx = blockIdx.x * 256 + threadIdx.x;
    int c = 0;
    if (idx < N_NODES) {
        c = g_count[idx];
        g_dis[idx] = rsqrtf((float)(c + 1));   // + self loop
    }
    int lane = threadIdx.x & 31, wid = threadIdx.x >> 5;
    int v = c;
#pragma unroll
    for (int o = 16; o > 0; o >>= 1) v += __shfl_down_sync(0xffffffffu, v, o);
    if (lane == 0) wsum[wid] = v;
    __syncthreads();
    if (threadIdx.x == 0) {
        int s = 0;
#pragma unroll
        for (int w = 0; w < 8; w++) s += wsum[w];
        g_bsum[blockIdx.x] = s;
    }
}

// ---------------- scan phase B: scan 196 partials (1 block) ----------------
__global__ __launch_bounds__(256) void scanB_kernel() {
    __shared__ int wsum[8];
    int t = threadIdx.x;
    int v = (t < SCAN_BLOCKS) ? g_bsum[t] : 0;
    int lane = t & 31, wid = t >> 5;
    int inc = v;
#pragma unroll
    for (int o = 1; o < 32; o <<= 1) {
        int n = __shfl_up_sync(0xffffffffu, inc, o);
        if (lane >= o) inc += n;
    }
    if (lane == 31) wsum[wid] = inc;
    __syncthreads();
    if (wid == 0 && lane < 8) {
        int w = wsum[lane];
#pragma unroll
        for (int o = 1; o < 8; o <<= 1) {
            int n = __shfl_up_sync(0xffu, w, o);
            if (lane >= o) w += n;
        }
        wsum[lane] = w;
    }
    __syncthreads();
    int incl = inc + (wid > 0 ? wsum[wid - 1] : 0);
    if (t < SCAN_BLOCKS) g_bpre[t] = incl - v;   // exclusive
    if (t == 255) g_off[N_NODES] = wsum[7];      // total
}

// ---------------- scan phase C: per-block local scan + offsets ----------------
__global__ __launch_bounds__(256) void scanC_kernel() {
    __shared__ int wsum[8];
    int idx = blockIdx.x * 256 + threadIdx.x;
    int c = (idx < N_NODES) ? g_count[idx] : 0;
    int lane = threadIdx.x & 31, wid = threadIdx.x >> 5;
    int inc = c;
#pragma unroll
    for (int o = 1; o < 32; o <<= 1) {
        int n = __shfl_up_sync(0xffffffffu, inc, o);
        if (lane >= o) inc += n;
    }
    if (lane == 31) wsum[wid] = inc;
    __syncthreads();
    if (wid == 0 && lane < 8) {
        int w = wsum[lane];
#pragma unroll
        for (int o = 1; o < 8; o <<= 1) {
            int n = __shfl_up_sync(0xffu, w, o);
            if (lane >= o) w += n;
        }
        wsum[lane] = w;
    }
    __syncthreads();
    int excl = inc - c + (wid > 0 ? wsum[wid - 1] : 0) + g_bpre[blockIdx.x];
    if (idx < N_NODES) {
        g_off[idx] = excl;
        g_cursor[idx] = excl;
    }
}

__global__ void csr_fill_kernel(const int* __restrict__ src, const int* __restrict__ dst) {
    int e = blockIdx.x * blockDim.x + threadIdx.x;
    if (e < N_EDGES) {
        int d = dst[e];
        int pos = atomicAdd(&g_cursor[d], 1);
        g_csr_src[pos] = src[e];
    }
}

// ---------------- GEMM: g_hw[rows] = (act(in[rows]) @ W) * dis[row] ----------
#define TR 64
#define HT_STRIDE (TR + 4)
#define GEMM_SMEM ((DIM * DIM + DIM * HT_STRIDE) * 4)

__global__ __launch_bounds__(384) void gemm_kernel(const float* __restrict__ in,
                                                   const float* __restrict__ Wl,
                                                   int apply_bn) {
    extern __shared__ float smem[];
    float* Ws = smem;                              // [96][96]
    float* Ht = smem + DIM * DIM;                  // [96][68]

    int t = threadIdx.x;
    for (int i = t; i < DIM * DIM; i += 384) Ws[i] = Wl[i];

    const float* __restrict__ inp = apply_bn ? g_agg : in;
    int row0 = blockIdx.x * TR;
    for (int i = t; i < TR * DIM; i += 384) {
        int r = i / DIM, c = i % DIM;
        int rr = row0 + r;
        float v = (rr < N_NODES) ? inp[(size_t)rr * DIM + c] : 0.0f;
        if (apply_bn) v = fmaxf(fmaf(v, g_bn[c], g_bn[DIM + c]), 0.0f);
        Ht[c * HT_STRIDE + r] = v;
    }
    __syncthreads();

    int cp = t % 48;        // column pair id
    int rg = t / 48;        // row group 0..7
    int c0 = cp * 2;
    int r0 = rg * 8;

    float acc[8][2];
#pragma unroll
    for (int j = 0; j < 8; j++) { acc[j][0] = 0.0f; acc[j][1] = 0.0f; }

#pragma unroll 4
    for (int k = 0; k < DIM; k++) {
        float2 w = *(const float2*)&Ws[k * DIM + c0];
        float4 h0 = *(const float4*)&Ht[k * HT_STRIDE + r0];
        float4 h1 = *(const float4*)&Ht[k * HT_STRIDE + r0 + 4];
        float hv[8] = {h0.x, h0.y, h0.z, h0.w, h1.x, h1.y, h1.z, h1.w};
#pragma unroll
        for (int j = 0; j < 8; j++) {
            acc[j][0] = fmaf(hv[j], w.x, acc[j][0]);
            acc[j][1] = fmaf(hv[j], w.y, acc[j][1]);
        }
    }

#pragma unroll
    for (int j = 0; j < 8; j++) {
        int rr = row0 + r0 + j;
        if (rr < N_NODES) {
            float dv = g_dis[rr];
            *(float2*)&g_hw[(size_t)rr * DIM + c0] =
                make_float2(acc[j][0] * dv, acc[j][1] * dv);
        }
    }
}

// ---------------- gather: agg[d] = dis[d]*(sum_{N(d)+self} hw') + b
// float4 per lane (lanes 0..23), grid-stride, register BN stats,
// BN-finalize fused into last block. ----------------
__global__ __launch_bounds__(256) void gather_kernel(const float* __restrict__ bl,
                                                     const float* __restrict__ gamma,
                                                     const float* __restrict__ beta) {
    __shared__ float ssum[DIM], ssq[DIM];
    __shared__ bool s_last;
    int t = threadIdx.x;
    if (t < DIM) { ssum[t] = 0.0f; ssq[t] = 0.0f; }
    __syncthreads();

    int lane = t & 31, warp = t >> 5;
    int gwarp = blockIdx.x * 8 + warp;
    const int TOT_WARPS = GATHER_BLOCKS * 8;

    if (lane < 24) {
        int col = lane * 4;
        float4 b4 = *(const float4*)&bl[col];
        float4 st = make_float4(0.f, 0.f, 0.f, 0.f);
        float4 sq = make_float4(0.f, 0.f, 0.f, 0.f);

        for (int node = gwarp; node < N_NODES; node += TOT_WARPS) {
            int j    = g_off[node];
            int rend = g_off[node + 1];
            float4 acc = make_float4(0.f, 0.f, 0.f, 0.f);
            for (; j + 4 <= rend; j += 4) {
                int s0 = g_csr_src[j],     s1 = g_csr_src[j + 1];
                int s2 = g_csr_src[j + 2], s3 = g_csr_src[j + 3];
                float4 v0 = *(const float4*)&g_hw[(size_t)s0 * DIM + col];
                float4 v1 = *(const float4*)&g_hw[(size_t)s1 * DIM + col];
                float4 v2 = *(const float4*)&g_hw[(size_t)s2 * DIM + col];
                float4 v3 = *(const float4*)&g_hw[(size_t)s3 * DIM + col];
                acc.x += (v0.x + v1.x) + (v2.x + v3.x);
                acc.y += (v0.y + v1.y) + (v2.y + v3.y);
                acc.z += (v0.z + v1.z) + (v2.z + v3.z);
                acc.w += (v0.w + v1.w) + (v2.w + v3.w);
            }
            for (; j < rend; j++) {
                int s0 = g_csr_src[j];
                float4 v0 = *(const float4*)&g_hw[(size_t)s0 * DIM + col];
                acc.x += v0.x; acc.y += v0.y; acc.z += v0.z; acc.w += v0.w;
            }
            // self loop (hw' already includes dis[node])
            float4 vs = *(const float4*)&g_hw[(size_t)node * DIM + col];
            acc.x += vs.x; acc.y += vs.y; acc.z += vs.z; acc.w += vs.w;

            float dd = g_dis[node];
            float4 r;
            r.x = fmaf(acc.x, dd, b4.x);
            r.y = fmaf(acc.y, dd, b4.y);
            r.z = fmaf(acc.z, dd, b4.z);
            r.w = fmaf(acc.w, dd, b4.w);
            *(float4*)&g_agg[(size_t)node * DIM + col] = r;

            st.x += r.x; st.y += r.y; st.z += r.z; st.w += r.w;
            sq.x = fmaf(r.x, r.x, sq.x); sq.y = fmaf(r.y, r.y, sq.y);
            sq.z = fmaf(r.z, r.z, sq.z); sq.w = fmaf(r.w, r.w, sq.w);
        }
        atomicAdd(&ssum[col + 0], st.x); atomicAdd(&ssum[col + 1], st.y);
        atomicAdd(&ssum[col + 2], st.z); atomicAdd(&ssum[col + 3], st.w);
        atomicAdd(&ssq[col + 0], sq.x);  atomicAdd(&ssq[col + 1], sq.y);
        atomicAdd(&ssq[col + 2], sq.z);  atomicAdd(&ssq[col + 3], sq.w);
    }
    __syncthreads();
    if (t < DIM) {
        atomicAdd(&g_stats[t], ssum[t]);
        atomicAdd(&g_stats[DIM + t], ssq[t]);
    }

    // ---- last-block BN finalize ----
    __threadfence();
    __syncthreads();
    if (t == 0) {
        unsigned v = atomicAdd(&g_done, 1u);
        s_last = (v == (unsigned)(gridDim.x - 1));
    }
    __syncthreads();
    if (s_last) {
        if (t < DIM) {
            float s  = atomicAdd(&g_stats[t], 0.0f);        // coherent L2 read
            float s2 = atomicAdd(&g_stats[DIM + t], 0.0f);
            float mu  = s * (1.0f / N_NODES);
            float var = s2 * (1.0f / N_NODES) - mu * mu;
            float rs  = rsqrtf(var + BN_EPS);
            float a   = rs * gamma[t];
            g_bn[t] = a;
            g_bn[DIM + t] = beta[t] - mu * a;
            g_stats[t] = 0.0f;
            g_stats[DIM + t] = 0.0f;
        }
        if (t == 0) g_done = 0;
    }
}

// ---------------- pooling: BN + ReLU + segment mean (sorted batch) --------
__global__ __launch_bounds__(384) void pool_kernel(const int* __restrict__ batch,
                                                   float* __restrict__ out) {
    int c = threadIdx.x;   // 0..95
    int ty = threadIdx.y;  // 0..3
    int r0 = blockIdx.x * 128;
    int rend = r0 + 128; if (rend > N_NODES) rend = N_NODES;
    float a = g_bn[c], cc = g_bn[DIM + c];
    float acc = 0.0f;
    int cg = -1;
    for (int r = r0 + ty; r < rend; r += 4) {
        float v = fmaxf(fmaf(g_agg[(size_t)r * DIM + c], a, cc), 0.0f);
        int g = batch[r];
        if (g != cg) {
            if (cg >= 0) atomicAdd(&out[cg * DIM + c], acc);
            cg = g; acc = 0.0f;
        }
        acc += v;
    }
    if (cg >= 0) atomicAdd(&out[cg * DIM + c], acc);
}

__global__ void pool_div_kernel(float* __restrict__ out) {
    int i = blockIdx.x * blockDim.x + threadIdx.x;
    if (i < N_GRAPHS * DIM) {
        float cnt = g_cnt[i / DIM];
        out[i] = out[i] / fmaxf(cnt, 1.0f);
    }
}

// ---------------- launch ----------------
extern "C" void kernel_launch(void* const* d_in, const int* in_sizes, int n_in,
                              void* d_out, int out_size) {
    const float* x     = (const float*)d_in[0];
    const int*   eidx  = (const int*)d_in[1];
    const int*   batch = (const int*)d_in[2];
    const float* W     = (const float*)d_in[3];
    const float* b     = (const float*)d_in[4];
    const float* gamma = (const float*)d_in[5];
    const float* beta  = (const float*)d_in[6];
    float* out = (float*)d_out;

    const int* src = eidx;
    const int* dst = eidx + N_EDGES;

    static cudaStream_t s1 = nullptr;
    static cudaEvent_t ev_a = nullptr, ev_csr = nullptr;
    if (!s1) {
        cudaFuncSetAttribute(gemm_kernel,
                             cudaFuncAttributeMaxDynamicSharedMemorySize, GEMM_SMEM);
        cudaStreamCreateWithFlags(&s1, cudaStreamNonBlocking);
        cudaEventCreateWithFlags(&ev_a, cudaEventDisableTiming);
        cudaEventCreateWithFlags(&ev_csr, cudaEventDisableTiming);
    }

    // main (capture) stream: init -> deg -> scanA (produces dis needed by gemm0)
    init_kernel<<<(N_NODES + 255) / 256, 256>>>(out);
    deg_kernel<<<512, 256>>>(dst, batch);
    scanA_kernel<<<SCAN_BLOCKS, 256>>>();
    cudaEventRecord(ev_a, 0);

    // side stream: finish CSR build, overlapped with layer-0 GEMM
    cudaStreamWaitEvent(s1, ev_a, 0);
    scanB_kernel<<<1, 256, 0, s1>>>();
    scanC_kernel<<<SCAN_BLOCKS, 256, 0, s1>>>();
    csr_fill_kernel<<<(N_EDGES + 255) / 256, 256, 0, s1>>>(src, dst);
    cudaEventRecord(ev_csr, s1);

    int gemm_grid = (N_NODES + TR - 1) / TR;

    gemm_kernel<<<gemm_grid, 384, GEMM_SMEM>>>(x, W, 0);
    cudaStreamWaitEvent(0, ev_csr, 0);

    for (int l = 0; l < N_LAYERS; l++) {
        if (l > 0)
            gemm_kernel<<<gemm_grid, 384, GEMM_SMEM>>>(x, W + l * DIM * DIM, 1);
        gather_kernel<<<GATHER_BLOCKS, 256>>>(b + l * DIM, gamma + l * DIM,
                                              beta + l * DIM);
    }

    dim3 pool_blk(96, 4);
    pool_kernel<<<(N_NODES + 127) / 128, pool_blk>>>(batch, out);
    pool_div_kernel<<<(N_GRAPHS * DIM + 255) / 256, 256>>>(out);
}

// round 5
// speedup vs baseline: 1.8344x; 1.0313x over previous
#include <cuda_runtime.h>
#include <cuda_bf16.h>

#define N_NODES 50000
#define N_EDGES 800000
#define DIM 96
#define N_LAYERS 4
#define N_GRAPHS 256
#define BN_EPS 1e-5f
#define SCAN_BLOCKS ((N_NODES + 255) / 256)   // 196
#define GATHER_BLOCKS 1184                    // 148 SMs * 8

// ---------------- device scratch (no allocations allowed) ----------------
__device__ __nv_bfloat16 g_hwb[N_NODES * DIM]; // (h @ W) * dis[row], bf16
__device__ float g_agg[N_NODES * DIM];    // layer output pre-BN (fp32)
__device__ float g_dis[N_NODES];          // 1/sqrt(deg)
__device__ int   g_count[N_NODES];        // in-degree (excl. self loop)
__device__ int   g_off[N_NODES + 1];      // CSR row offsets
__device__ int   g_cursor[N_NODES];       // fill cursors
__device__ int   g_csr_src[N_EDGES];      // src ids grouped by dst
__device__ int   g_bsum[SCAN_BLOCKS];     // scan phase partials
__device__ int   g_bpre[SCAN_BLOCKS];     // scanned partials
__device__ float g_stats[2 * DIM];        // BN sum / sumsq
__device__ float g_bn[2 * DIM];           // BN affine: a, c  (y = a*x + c)
__device__ float g_cnt[N_GRAPHS];         // nodes per graph
__device__ unsigned g_done = 0;           // gather completion counter

// ---------------- init ----------------
__global__ void init_kernel(float* out) {
    int i = blockIdx.x * blockDim.x + threadIdx.x;
    if (i < N_NODES) g_count[i] = 0;
    if (i < 2 * DIM) g_stats[i] = 0.0f;
    if (i < N_GRAPHS) g_cnt[i] = 0.0f;
    if (i < N_GRAPHS * DIM) out[i] = 0.0f;
}

// ---------------- degree histogram + graph node counts ----------------
__global__ void deg_kernel(const int* __restrict__ dst, const int* __restrict__ batch) {
    int i = blockIdx.x * blockDim.x + threadIdx.x;
    int stride = gridDim.x * blockDim.x;
    for (int e = i; e < N_EDGES; e += stride)
        atomicAdd(&g_count[dst[e]], 1);
    for (int v = i; v < N_NODES; v += stride)
        atomicAdd(&g_cnt[batch[v]], 1.0f);
}

// ---------------- scan phase A: per-block partial sums + dis ----------------
__global__ __launch_bounds__(256) void scanA_kernel() {
    __shared__ int wsum[8];
    int idx = blockIdx.x * 256 + threadIdx.x;
    int c = 0;
    if (idx < N_NODES) {
        c = g_count[idx];
        g_dis[idx] = rsqrtf((float)(c + 1));   // + self loop
    }
    int lane = threadIdx.x & 31, wid = threadIdx.x >> 5;
    int v = c;
#pragma unroll
    for (int o = 16; o > 0; o >>= 1) v += __shfl_down_sync(0xffffffffu, v, o);
    if (lane == 0) wsum[wid] = v;
    __syncthreads();
    if (threadIdx.x == 0) {
        int s = 0;
#pragma unroll
        for (int w = 0; w < 8; w++) s += wsum[w];
        g_bsum[blockIdx.x] = s;
    }
}

// ---------------- scan phase B: scan 196 partials (1 block) ----------------
__global__ __launch_bounds__(256) void scanB_kernel() {
    __shared__ int wsum[8];
    int t = threadIdx.x;
    int v = (t < SCAN_BLOCKS) ? g_bsum[t] : 0;
    int lane = t & 31, wid = t >> 5;
    int inc = v;
#pragma unroll
    for (int o = 1; o < 32; o <<= 1) {
        int n = __shfl_up_sync(0xffffffffu, inc, o);
        if (lane >= o) inc += n;
    }
    if (lane == 31) wsum[wid] = inc;
    __syncthreads();
    if (wid == 0 && lane < 8) {
        int w = wsum[lane];
#pragma unroll
        for (int o = 1; o < 8; o <<= 1) {
            int n = __shfl_up_sync(0xffu, w, o);
            if (lane >= o) w += n;
        }
        wsum[lane] = w;
    }
    __syncthreads();
    int incl = inc + (wid > 0 ? wsum[wid - 1] : 0);
    if (t < SCAN_BLOCKS) g_bpre[t] = incl - v;   // exclusive
    if (t == 255) g_off[N_NODES] = wsum[7];      // total
}

// ---------------- scan phase C: per-block local scan + offsets ----------------
__global__ __launch_bounds__(256) void scanC_kernel() {
    __shared__ int wsum[8];
    int idx = blockIdx.x * 256 + threadIdx.x;
    int c = (idx < N_NODES) ? g_count[idx] : 0;
    int lane = threadIdx.x & 31, wid = threadIdx.x >> 5;
    int inc = c;
#pragma unroll
    for (int o = 1; o < 32; o <<= 1) {
        int n = __shfl_up_sync(0xffffffffu, inc, o);
        if (lane >= o) inc += n;
    }
    if (lane == 31) wsum[wid] = inc;
    __syncthreads();
    if (wid == 0 && lane < 8) {
        int w = wsum[lane];
#pragma unroll
        for (int o = 1; o < 8; o <<= 1) {
            int n = __shfl_up_sync(0xffu, w, o);
            if (lane >= o) w += n;
        }
        wsum[lane] = w;
    }
    __syncthreads();
    int excl = inc - c + (wid > 0 ? wsum[wid - 1] : 0) + g_bpre[blockIdx.x];
    if (idx < N_NODES) {
        g_off[idx] = excl;
        g_cursor[idx] = excl;
    }
}

__global__ void csr_fill_kernel(const int* __restrict__ src, const int* __restrict__ dst) {
    int e = blockIdx.x * blockDim.x + threadIdx.x;
    if (e < N_EDGES) {
        int d = dst[e];
        int pos = atomicAdd(&g_cursor[d], 1);
        g_csr_src[pos] = src[e];
    }
}

// ---------------- GEMM: g_hwb[rows] = bf16((act(in[rows]) @ W) * dis[row]) ----
#define TR 64
#define HT_STRIDE (TR + 4)
#define GEMM_SMEM ((DIM * DIM + DIM * HT_STRIDE) * 4)

__global__ __launch_bounds__(384) void gemm_kernel(const float* __restrict__ in,
                                                   const float* __restrict__ Wl,
                                                   int apply_bn) {
    extern __shared__ float smem[];
    float* Ws = smem;                              // [96][96]
    float* Ht = smem + DIM * DIM;                  // [96][68]

    int t = threadIdx.x;
    for (int i = t; i < DIM * DIM; i += 384) Ws[i] = Wl[i];

    const float* __restrict__ inp = apply_bn ? g_agg : in;
    int row0 = blockIdx.x * TR;
    for (int i = t; i < TR * DIM; i += 384) {
        int r = i / DIM, c = i % DIM;
        int rr = row0 + r;
        float v = (rr < N_NODES) ? inp[(size_t)rr * DIM + c] : 0.0f;
        if (apply_bn) v = fmaxf(fmaf(v, g_bn[c], g_bn[DIM + c]), 0.0f);
        Ht[c * HT_STRIDE + r] = v;
    }
    __syncthreads();

    int cp = t % 48;        // column pair id
    int rg = t / 48;        // row group 0..7
    int c0 = cp * 2;
    int r0 = rg * 8;

    float acc[8][2];
#pragma unroll
    for (int j = 0; j < 8; j++) { acc[j][0] = 0.0f; acc[j][1] = 0.0f; }

#pragma unroll 4
    for (int k = 0; k < DIM; k++) {
        float2 w = *(const float2*)&Ws[k * DIM + c0];
        float4 h0 = *(const float4*)&Ht[k * HT_STRIDE + r0];
        float4 h1 = *(const float4*)&Ht[k * HT_STRIDE + r0 + 4];
        float hv[8] = {h0.x, h0.y, h0.z, h0.w, h1.x, h1.y, h1.z, h1.w};
#pragma unroll
        for (int j = 0; j < 8; j++) {
            acc[j][0] = fmaf(hv[j], w.x, acc[j][0]);
            acc[j][1] = fmaf(hv[j], w.y, acc[j][1]);
        }
    }

#pragma unroll
    for (int j = 0; j < 8; j++) {
        int rr = row0 + r0 + j;
        if (rr < N_NODES) {
            float dv = g_dis[rr];
            __nv_bfloat162 bv = __floats2bfloat162_rn(acc[j][0] * dv, acc[j][1] * dv);
            *(__nv_bfloat162*)&g_hwb[(size_t)rr * DIM + c0] = bv;
        }
    }
}

// ---------------- gather: agg[d] = dis[d]*(sum_{N(d)+self} hw') + b
// bf16 rows, 4 cols/lane (lanes 0..23) via uint2 loads, fp32 accumulate,
// grid-stride, register BN stats, BN-finalize fused into last block. --------
__device__ __forceinline__ float4 ld_row4(const __nv_bfloat16* p) {
    uint2 u = *(const uint2*)p;
    __nv_bfloat162 p0 = *reinterpret_cast<__nv_bfloat162*>(&u.x);
    __nv_bfloat162 p1 = *reinterpret_cast<__nv_bfloat162*>(&u.y);
    float2 f0 = __bfloat1622float2(p0);
    float2 f1 = __bfloat1622float2(p1);
    return make_float4(f0.x, f0.y, f1.x, f1.y);
}

__global__ __launch_bounds__(256) void gather_kernel(const float* __restrict__ bl,
                                                     const float* __restrict__ gamma,
                                                     const float* __restrict__ beta) {
    __shared__ float ssum[DIM], ssq[DIM];
    __shared__ bool s_last;
    int t = threadIdx.x;
    if (t < DIM) { ssum[t] = 0.0f; ssq[t] = 0.0f; }
    __syncthreads();

    int lane = t & 31, warp = t >> 5;
    int gwarp = blockIdx.x * 8 + warp;
    const int TOT_WARPS = GATHER_BLOCKS * 8;

    if (lane < 24) {
        int col = lane * 4;
        float4 b4 = *(const float4*)&bl[col];
        float4 st = make_float4(0.f, 0.f, 0.f, 0.f);
        float4 sq = make_float4(0.f, 0.f, 0.f, 0.f);

        for (int node = gwarp; node < N_NODES; node += TOT_WARPS) {
            int j    = g_off[node];
            int rend = g_off[node + 1];
            float4 acc = make_float4(0.f, 0.f, 0.f, 0.f);
            for (; j + 4 <= rend; j += 4) {
                int s0 = g_csr_src[j],     s1 = g_csr_src[j + 1];
                int s2 = g_csr_src[j + 2], s3 = g_csr_src[j + 3];
                float4 v0 = ld_row4(&g_hwb[(size_t)s0 * DIM + col]);
                float4 v1 = ld_row4(&g_hwb[(size_t)s1 * DIM + col]);
                float4 v2 = ld_row4(&g_hwb[(size_t)s2 * DIM + col]);
                float4 v3 = ld_row4(&g_hwb[(size_t)s3 * DIM + col]);
                acc.x += (v0.x + v1.x) + (v2.x + v3.x);
                acc.y += (v0.y + v1.y) + (v2.y + v3.y);
                acc.z += (v0.z + v1.z) + (v2.z + v3.z);
                acc.w += (v0.w + v1.w) + (v2.w + v3.w);
            }
            for (; j < rend; j++) {
                int s0 = g_csr_src[j];
                float4 v0 = ld_row4(&g_hwb[(size_t)s0 * DIM + col]);
                acc.x += v0.x; acc.y += v0.y; acc.z += v0.z; acc.w += v0.w;
            }
            // self loop (hw' already includes dis[node])
            float4 vs = ld_row4(&g_hwb[(size_t)node * DIM + col]);
            acc.x += vs.x; acc.y += vs.y; acc.z += vs.z; acc.w += vs.w;

            float dd = g_dis[node];
            float4 r;
            r.x = fmaf(acc.x, dd, b4.x);
            r.y = fmaf(acc.y, dd, b4.y);
            r.z = fmaf(acc.z, dd, b4.z);
            r.w = fmaf(acc.w, dd, b4.w);
            *(float4*)&g_agg[(size_t)node * DIM + col] = r;

            st.x += r.x; st.y += r.y; st.z += r.z; st.w += r.w;
            sq.x = fmaf(r.x, r.x, sq.x); sq.y = fmaf(r.y, r.y, sq.y);
            sq.z = fmaf(r.z, r.z, sq.z); sq.w = fmaf(r.w, r.w, sq.w);
        }
        atomicAdd(&ssum[col + 0], st.x); atomicAdd(&ssum[col + 1], st.y);
        atomicAdd(&ssum[col + 2], st.z); atomicAdd(&ssum[col + 3], st.w);
        atomicAdd(&ssq[col + 0], sq.x);  atomicAdd(&ssq[col + 1], sq.y);
        atomicAdd(&ssq[col + 2], sq.z);  atomicAdd(&ssq[col + 3], sq.w);
    }
    __syncthreads();
    if (t < DIM) {
        atomicAdd(&g_stats[t], ssum[t]);
        atomicAdd(&g_stats[DIM + t], ssq[t]);
    }

    // ---- last-block BN finalize ----
    __threadfence();
    __syncthreads();
    if (t == 0) {
        unsigned v = atomicAdd(&g_done, 1u);
        s_last = (v == (unsigned)(gridDim.x - 1));
    }
    __syncthreads();
    if (s_last) {
        if (t < DIM) {
            float s  = atomicAdd(&g_stats[t], 0.0f);        // coherent L2 read
            float s2 = atomicAdd(&g_stats[DIM + t], 0.0f);
            float mu  = s * (1.0f / N_NODES);
            float var = s2 * (1.0f / N_NODES) - mu * mu;
            float rs  = rsqrtf(var + BN_EPS);
            float a   = rs * gamma[t];
            g_bn[t] = a;
            g_bn[DIM + t] = beta[t] - mu * a;
            g_stats[t] = 0.0f;
            g_stats[DIM + t] = 0.0f;
        }
        if (t == 0) g_done = 0;
    }
}

// ---------------- pooling: BN + ReLU + segment mean (sorted batch) --------
__global__ __launch_bounds__(384) void pool_kernel(const int* __restrict__ batch,
                                                   float* __restrict__ out) {
    int c = threadIdx.x;   // 0..95
    int ty = threadIdx.y;  // 0..3
    int r0 = blockIdx.x * 128;
    int rend = r0 + 128; if (rend > N_NODES) rend = N_NODES;
    float a = g_bn[c], cc = g_bn[DIM + c];
    float acc = 0.0f;
    int cg = -1;
    for (int r = r0 + ty; r < rend; r += 4) {
        float v = fmaxf(fmaf(g_agg[(size_t)r * DIM + c], a, cc), 0.0f);
        int g = batch[r];
        if (g != cg) {
            if (cg >= 0) atomicAdd(&out[cg * DIM + c], acc);
            cg = g; acc = 0.0f;
        }
        acc += v;
    }
    if (cg >= 0) atomicAdd(&out[cg * DIM + c], acc);
}

__global__ void pool_div_kernel(float* __restrict__ out) {
    int i = blockIdx.x * blockDim.x + threadIdx.x;
    if (i < N_GRAPHS * DIM) {
        float cnt = g_cnt[i / DIM];
        out[i] = out[i] / fmaxf(cnt, 1.0f);
    }
}

// ---------------- launch ----------------
extern "C" void kernel_launch(void* const* d_in, const int* in_sizes, int n_in,
                              void* d_out, int out_size) {
    const float* x     = (const float*)d_in[0];
    const int*   eidx  = (const int*)d_in[1];
    const int*   batch = (const int*)d_in[2];
    const float* W     = (const float*)d_in[3];
    const float* b     = (const float*)d_in[4];
    const float* gamma = (const float*)d_in[5];
    const float* beta  = (const float*)d_in[6];
    float* out = (float*)d_out;

    const int* src = eidx;
    const int* dst = eidx + N_EDGES;

    static cudaStream_t s1 = nullptr;
    static cudaEvent_t ev_a = nullptr, ev_csr = nullptr;
    if (!s1) {
        cudaFuncSetAttribute(gemm_kernel,
                             cudaFuncAttributeMaxDynamicSharedMemorySize, GEMM_SMEM);
        cudaStreamCreateWithFlags(&s1, cudaStreamNonBlocking);
        cudaEventCreateWithFlags(&ev_a, cudaEventDisableTiming);
        cudaEventCreateWithFlags(&ev_csr, cudaEventDisableTiming);
    }

    // main (capture) stream: init -> deg -> scanA (produces dis needed by gemm0)
    init_kernel<<<(N_NODES + 255) / 256, 256>>>(out);
    deg_kernel<<<512, 256>>>(dst, batch);
    scanA_kernel<<<SCAN_BLOCKS, 256>>>();
    cudaEventRecord(ev_a, 0);

    // side stream: finish CSR build, overlapped with layer-0 GEMM
    cudaStreamWaitEvent(s1, ev_a, 0);
    scanB_kernel<<<1, 256, 0, s1>>>();
    scanC_kernel<<<SCAN_BLOCKS, 256, 0, s1>>>();
    csr_fill_kernel<<<(N_EDGES + 255) / 256, 256, 0, s1>>>(src, dst);
    cudaEventRecord(ev_csr, s1);

    int gemm_grid = (N_NODES + TR - 1) / TR;

    gemm_kernel<<<gemm_grid, 384, GEMM_SMEM>>>(x, W, 0);
    cudaStreamWaitEvent(0, ev_csr, 0);

    for (int l = 0; l < N_LAYERS; l++) {
        if (l > 0)
            gemm_kernel<<<gemm_grid, 384, GEMM_SMEM>>>(x, W + l * DIM * DIM, 1);
        gather_kernel<<<GATHER_BLOCKS, 256>>>(b + l * DIM, gamma + l * DIM,
                                              beta + l * DIM);
    }

    dim3 pool_blk(96, 4);
    pool_kernel<<<(N_NODES + 127) / 128, pool_blk>>>(batch, out);
    pool_div_kernel<<<(N_GRAPHS * DIM + 255) / 256, 256>>>(out);
}